// round 14
// baseline (speedup 1.0000x reference)
#include <cuda_runtime.h>
#include <cuda_fp16.h>
#include <stdint.h>

#define B_TOT   16384
#define N_IN    6
#define N_MF    5
#define N_FUZZ  30
#define N_RULES 2048
#define NSPLIT  32
#define RPS     (N_RULES / NSPLIT)   // 64 rules per split
#define TPB     128
#define EPB     512                  // 4 elems per thread
#define NGROUP  (B_TOT / EPB)        // 32
#define EPS_F   1e-12f
#define SQRT_LOG2E 1.2011224087864498f   // sqrt(log2(e))
#define GRP_RULES 8                  // rules per fp16 accumulation group

// Scratch (__device__ globals: no allocation allowed)
__device__ float4 g_partial[NSPLIT * B_TOT];   // {l1, d0, d1, pad}
__device__ int    g_cnt[NGROUP];               // zero-init; reset after use

static __device__ __forceinline__ float ex2(float v) {
    float r; asm("ex2.approx.ftz.f32 %0, %1;" : "=f"(r) : "f"(v)); return r;
}

// ---------------------------------------------------------------------------
// Single fused kernel. 4 elems/thread: the LDS *instruction* count per rule
// (the measured binder: ~2.1 cyc/SMSP per warp-LDS) serves 128 elems/warp
// instead of 64 -> LDS-issue floor halves vs the R12 best.
//  - SMEM fuzz word (idx, t) = uint2 {h2(e0,e1), h2(e2,e3)}, e0 = base+4t.
//    One LDS.64 gather serves 4 elems. Row stride 1024B.
//  - Rule record: ONE uint4 {4 bytes of 4*idx, 2 bytes of 4*idx,
//    half2(ow0,ow0), half2(ow1,ow1)}; __byte_perm(0,w,0x004k) yields
//    (4*idx)<<8 = idx<<10 (PRMT is free: ALU pipe idle).
//  - fp16 group accumulation (GRP_RULES rules) flushed to fp32: minimal
//    register live-set (the killer of all prior 4-elem attempts).
//  - Fuzzify pairwise (2 elems at a time, STS.32 into word lo/hi) to avoid
//    caching 24 x-values in registers.
//  - __launch_bounds__(128, 7): cap ~73 regs, 7 blocks/SM (smem 31KB*7 OK).
//  - Last-arriving split block per group finalizes (deterministic order).
// ---------------------------------------------------------------------------
__global__ __launch_bounds__(TPB, 7) void anfis_fused_kernel(
    const float* __restrict__ x,
    const float* __restrict__ mf_centers,
    const float* __restrict__ mf_scales,
    const float* __restrict__ out_centers,
    const int*   __restrict__ input_rules,
    const int*   __restrict__ output_rules,
    float* __restrict__ out)
{
    __shared__ uint2   s_fuzz[N_FUZZ * TPB];  // 30 KB
    __shared__ uint4   s_pk[RPS];             // 1 KB: one record per rule
    __shared__ float2  s_cs[N_FUZZ];          // {c*a, a}
    __shared__ int     s_flag;

    const int tid   = threadIdx.x;
    const int grp   = blockIdx.x;
    const int split = blockIdx.y;
    const int base  = grp * EPB;
    const int e0    = base + 4 * tid;

    // ---- stage this split's rules: byte-packed 4*idx + half2-dup ow ----
    if (tid < RPS) {
        const int r = split * RPS + tid;
        const int* ir = input_rules + r * N_IN;
        unsigned w0 = ((unsigned)ir[0] * 4)
                    | (((unsigned)ir[1] * 4) << 8)
                    | (((unsigned)ir[2] * 4) << 16)
                    | (((unsigned)ir[3] * 4) << 24);
        unsigned w1 = ((unsigned)ir[4] * 4)
                    | (((unsigned)ir[5] * 4) << 8);
        float ow0 = out_centers[output_rules[r * 2 + 0]];
        float ow1 = out_centers[output_rules[r * 2 + 1]];
        __half2 ow0h = __floats2half2_rn(ow0, ow0);
        __half2 ow1h = __floats2half2_rn(ow1, ow1);
        s_pk[tid] = make_uint4(w0, w1,
                               *reinterpret_cast<uint32_t*>(&ow0h),
                               *reinterpret_cast<uint32_t*>(&ow1h));
    }
    // ---- membership-function constants: a = sqrt(log2e)/s ----
    if (tid < N_FUZZ) {
        float c = mf_centers[tid];
        float s = mf_scales[tid];
        float a = __fdividef(SQRT_LOG2E, s);
        s_cs[tid] = make_float2(c * a, a);
    }
    __syncthreads();

    // ---- fuzzify 4 elems pairwise (keeps only 12 x regs live) ----
    #pragma unroll
    for (int ep = 0; ep < 2; ep++) {
        const float* xs = x + (size_t)(e0 + 2 * ep) * N_IN;
        float xa[N_IN], xb[N_IN];
        #pragma unroll
        for (int i = 0; i < N_IN; i++) {
            xa[i] = __ldg(&xs[i]);
            xb[i] = __ldg(&xs[N_IN + i]);
        }
        uint32_t* dst = reinterpret_cast<uint32_t*>(s_fuzz) + tid * 2 + ep;
        #pragma unroll
        for (int i = 0; i < N_IN; i++) {
            #pragma unroll
            for (int j = 0; j < N_MF; j++) {
                float2 cs = s_cs[i * N_MF + j];
                float ta = fmaf(xa[i], cs.y, -cs.x);
                float tb = fmaf(xb[i], cs.y, -cs.x);
                __half2 h = __floats2half2_rn(ex2(-ta * ta), ex2(-tb * tb));
                dst[(i * N_MF + j) * TPB * 2] = *reinterpret_cast<uint32_t*>(&h);
            }
        }
    }
    __syncthreads();

    // ---- rule loop: 1 LDS.128 bcast + 6 LDS.64 gathers per rule (128 el) ----
    const char* fb = reinterpret_cast<const char*>(s_fuzz) + tid * 8;
    float laA = 0.f, lbA = 0.f, d0aA = 0.f, d0bA = 0.f, d1aA = 0.f, d1bA = 0.f;
    float laB = 0.f, lbB = 0.f, d0aB = 0.f, d0bB = 0.f, d1aB = 0.f, d1bB = 0.f;

    const __half2 hzero = __float2half2_rn(0.f);

    for (int kb = 0; kb < RPS; kb += GRP_RULES) {
        __half2 lhA = hzero, d0hA = hzero, d1hA = hzero;   // elems e0,e1
        __half2 lhB = hzero, d0hB = hzero, d1hB = hzero;   // elems e2,e3

        #pragma unroll
        for (int u = 0; u < GRP_RULES; u++) {
            const uint4 pk = s_pk[kb + u];         // single LDS.128 broadcast

            // PRMT: byte_k(w) << 8 = (4*idx)<<8 = idx<<10 (1024B row offset)
            uint2 f0 = *reinterpret_cast<const uint2*>(fb + __byte_perm(0u, pk.x, 0x0040));
            uint2 f1 = *reinterpret_cast<const uint2*>(fb + __byte_perm(0u, pk.x, 0x0050));
            uint2 f2 = *reinterpret_cast<const uint2*>(fb + __byte_perm(0u, pk.x, 0x0060));
            uint2 f3 = *reinterpret_cast<const uint2*>(fb + __byte_perm(0u, pk.x, 0x0070));
            uint2 f4 = *reinterpret_cast<const uint2*>(fb + __byte_perm(0u, pk.y, 0x0040));
            uint2 f5 = *reinterpret_cast<const uint2*>(fb + __byte_perm(0u, pk.y, 0x0050));

            __half2 mA = __hmin2(__hmin2(__hmin2(*(__half2*)&f0.x, *(__half2*)&f1.x),
                                         __hmin2(*(__half2*)&f2.x, *(__half2*)&f3.x)),
                                 __hmin2(*(__half2*)&f4.x, *(__half2*)&f5.x));
            __half2 mB = __hmin2(__hmin2(__hmin2(*(__half2*)&f0.y, *(__half2*)&f1.y),
                                         __hmin2(*(__half2*)&f2.y, *(__half2*)&f3.y)),
                                 __hmin2(*(__half2*)&f4.y, *(__half2*)&f5.y));

            __half2 ow0 = *reinterpret_cast<const __half2*>(&pk.z);
            __half2 ow1 = *reinterpret_cast<const __half2*>(&pk.w);

            lhA  = __hadd2(lhA, mA);           lhB  = __hadd2(lhB, mB);
            d0hA = __hfma2(mA, ow0, d0hA);     d0hB = __hfma2(mB, ow0, d0hB);
            d1hA = __hfma2(mA, ow1, d1hA);     d1hB = __hfma2(mB, ow1, d1hB);
        }

        float2 t;
        t = __half22float2(lhA);  laA  += t.x;  lbA  += t.y;
        t = __half22float2(d0hA); d0aA += t.x;  d0bA += t.y;
        t = __half22float2(d1hA); d1aA += t.x;  d1bA += t.y;
        t = __half22float2(lhB);  laB  += t.x;  lbB  += t.y;
        t = __half22float2(d0hB); d0aB += t.x;  d0bB += t.y;
        t = __half22float2(d1hB); d1aB += t.x;  d1bB += t.y;
    }

    // ---- write partials: 4 consecutive float4 = 64B coalesced ----
    {
        float4* p = &g_partial[split * B_TOT + e0];
        p[0] = make_float4(laA, d0aA, d1aA, 0.f);
        p[1] = make_float4(lbA, d0bA, d1bA, 0.f);
        p[2] = make_float4(laB, d0aB, d1aB, 0.f);
        p[3] = make_float4(lbB, d0bB, d1bB, 0.f);
    }

    // ---- last-block finalize (deterministic fixed-order summation) ----
    __threadfence();
    __syncthreads();
    if (tid == 0) {
        int old = atomicAdd(&g_cnt[grp], 1);
        s_flag = (old == NSPLIT - 1);
    }
    __syncthreads();

    if (s_flag) {
        __threadfence();
        #pragma unroll
        for (int e = 0; e < 4; e++) {
            const int b = e0 + e;
            float l = 0.f, s0 = 0.f, s1 = 0.f;
            #pragma unroll
            for (int s = 0; s < NSPLIT; s++) {
                float4 p = __ldcg(&g_partial[s * B_TOT + b]);
                l += p.x; s0 += p.y; s1 += p.z;
            }
            float inv = __fdividef(1.0f, fmaxf(l, EPS_F));
            float o0 = tanhf(s0 * inv) * 4.0f;            // scale 4.0, center 0.0
            float o1 = tanhf(s1 * inv) * 0.75f + 0.75f;   // scale .75, center .75
            reinterpret_cast<float2*>(out)[b] = make_float2(o0, o1);
        }
        if (tid == 0) g_cnt[grp] = 0;   // reset for next graph replay
    }
}

// ---------------------------------------------------------------------------
extern "C" void kernel_launch(void* const* d_in, const int* in_sizes, int n_in,
                              void* d_out, int out_size) {
    const float* x            = (const float*)d_in[0];
    const float* mf_centers   = (const float*)d_in[1];
    const float* mf_scales    = (const float*)d_in[2];
    const float* out_centers  = (const float*)d_in[3];
    const int*   input_rules  = (const int*)d_in[4];
    const int*   output_rules = (const int*)d_in[5];

    dim3 grid(NGROUP, NSPLIT);
    anfis_fused_kernel<<<grid, TPB>>>(x, mf_centers, mf_scales, out_centers,
                                      input_rules, output_rules, (float*)d_out);
}

// round 15
// speedup vs baseline: 1.0741x; 1.0741x over previous
#include <cuda_runtime.h>
#include <cuda_fp16.h>
#include <stdint.h>

#define B_TOT   16384
#define N_IN    6
#define N_MF    5
#define N_FUZZ  30
#define N_RULES 2048
#define NSPLIT  16
#define RPS     (N_RULES / NSPLIT)   // 128 rules per split
#define TPB     128
#define EPB     256                  // 2 elems per thread (half2)
#define NGROUP  (B_TOT / EPB)        // 64
#define EPS_F   1e-12f
#define SQRT_LOG2E 1.2011224087864498f   // sqrt(log2(e))
#define GRP_RULES 8                  // rules per fp16 accumulation group

// Scratch (__device__ globals: no allocation allowed)
__device__ float4 g_partial[NSPLIT * B_TOT];   // {l1, d0, d1, pad}
__device__ int    g_cnt[NGROUP];               // zero-init; reset after use

static __device__ __forceinline__ float ex2(float v) {
    float r; asm("ex2.approx.ftz.f32 %0, %1;" : "=f"(r) : "f"(v)); return r;
}

// ---------------------------------------------------------------------------
// Single fused kernel — the measured-best configuration (R12).
//  - Fuzz table in SMEM as half2 {fuzz[b0], fuzz[b1]}, b1 = b0+128; one
//    LDS.32 gather serves 2 elems; bank = tid mod 32 -> conflict-free.
//  - Rule record uint4: {x: 4 bytes of 2*idx, y: 2 bytes of 2*idx,
//    z: half2(ow0,ow0), w: half2(ow1,ow1)}. __byte_perm(0, word, 0x004k)
//    yields (2*idx)<<8 = idx<<9 (512B row offset) in ONE instruction;
//    PRMT rides the idle ALU pipe (measured free vs an extra LDS).
//  - Accumulation: per rule 1 HADD2 + 2 HFMA2 in fp16; group sums of
//    GRP_RULES rules flushed to fp32. Rule-level rounding is zero-mean;
//    measured rel_err 7.47e-4 (deterministic: fixed seed + fixed order).
//  - Last-arriving split block per group finalizes (deterministic order).
// ---------------------------------------------------------------------------
__global__ __launch_bounds__(TPB) void anfis_fused_kernel(
    const float* __restrict__ x,
    const float* __restrict__ mf_centers,
    const float* __restrict__ mf_scales,
    const float* __restrict__ out_centers,
    const int*   __restrict__ input_rules,
    const int*   __restrict__ output_rules,
    float* __restrict__ out)
{
    __shared__ __half2 s_fuzz[N_FUZZ * TPB];  // 15 KB
    __shared__ uint4   s_pk[RPS];             // 2 KB: one record per rule
    __shared__ float2  s_cs[N_FUZZ];          // {c*a, a}
    __shared__ int     s_flag;

    const int tid   = threadIdx.x;
    const int grp   = blockIdx.x;
    const int split = blockIdx.y;
    const int b0    = grp * EPB + tid;
    const int b1    = b0 + TPB;

    // ---- stage this split's rules: byte-packed 2*idx + half2-dup ow ----
    if (tid < RPS) {
        const int r = split * RPS + tid;
        const int* ir = input_rules + r * N_IN;
        unsigned w0 = ((unsigned)ir[0] * 2)
                    | (((unsigned)ir[1] * 2) << 8)
                    | (((unsigned)ir[2] * 2) << 16)
                    | (((unsigned)ir[3] * 2) << 24);
        unsigned w1 = ((unsigned)ir[4] * 2)
                    | (((unsigned)ir[5] * 2) << 8);
        float ow0 = out_centers[output_rules[r * 2 + 0]];
        float ow1 = out_centers[output_rules[r * 2 + 1]];
        __half2 ow0h = __floats2half2_rn(ow0, ow0);
        __half2 ow1h = __floats2half2_rn(ow1, ow1);
        s_pk[tid] = make_uint4(w0, w1,
                               *reinterpret_cast<uint32_t*>(&ow0h),
                               *reinterpret_cast<uint32_t*>(&ow1h));
    }
    // ---- membership-function constants: a = sqrt(log2e)/s ----
    if (tid < N_FUZZ) {
        float c = mf_centers[tid];
        float s = mf_scales[tid];
        float a = __fdividef(SQRT_LOG2E, s);
        s_cs[tid] = make_float2(c * a, a);
    }
    __syncthreads();

    // ---- fuzzify both batch elems: exp(-z^2) = ex2(-(x*a - c*a)^2) ----
    {
        float xa[N_IN], xb[N_IN];
        #pragma unroll
        for (int i = 0; i < N_IN; i++) {
            xa[i] = x[b0 * N_IN + i];
            xb[i] = x[b1 * N_IN + i];
        }
        #pragma unroll
        for (int i = 0; i < N_IN; i++) {
            #pragma unroll
            for (int j = 0; j < N_MF; j++) {
                float2 cs = s_cs[i * N_MF + j];      // LDS.64 broadcast
                float ta = fmaf(xa[i], cs.y, -cs.x);
                float tb = fmaf(xb[i], cs.y, -cs.x);
                s_fuzz[(i * N_MF + j) * TPB + tid] =
                    __floats2half2_rn(ex2(-ta * ta), ex2(-tb * tb));
            }
        }
    }
    __syncthreads();

    // ---- rule loop: 1 LDS.128 bcast + 6 LDS.32 gathers per rule;
    //      fp16 group accumulators flushed to fp32 every GRP_RULES rules ----
    const char* fb = reinterpret_cast<const char*>(s_fuzz) + tid * 4;
    float la = 0.f, lb = 0.f;
    float d0a = 0.f, d0b = 0.f;
    float d1a = 0.f, d1b = 0.f;

    const __half2 hzero = __float2half2_rn(0.f);

    for (int kb = 0; kb < RPS; kb += GRP_RULES) {
        __half2 lh  = hzero;
        __half2 d0h = hzero;
        __half2 d1h = hzero;

        #pragma unroll
        for (int u = 0; u < GRP_RULES; u++) {
            const uint4 pk = s_pk[kb + u];         // single LDS.128 broadcast

            // __byte_perm(0, w, 0x004k): byte_k(w) << 8 = (2*idx)<<8 = idx<<9
            __half2 f0 = *reinterpret_cast<const __half2*>(fb + __byte_perm(0u, pk.x, 0x0040));
            __half2 f1 = *reinterpret_cast<const __half2*>(fb + __byte_perm(0u, pk.x, 0x0050));
            __half2 f2 = *reinterpret_cast<const __half2*>(fb + __byte_perm(0u, pk.x, 0x0060));
            __half2 f3 = *reinterpret_cast<const __half2*>(fb + __byte_perm(0u, pk.x, 0x0070));
            __half2 f4 = *reinterpret_cast<const __half2*>(fb + __byte_perm(0u, pk.y, 0x0040));
            __half2 f5 = *reinterpret_cast<const __half2*>(fb + __byte_perm(0u, pk.y, 0x0050));

            __half2 w = __hmin2(__hmin2(__hmin2(f0, f1), __hmin2(f2, f3)),
                                __hmin2(f4, f5));

            __half2 ow0 = *reinterpret_cast<const __half2*>(&pk.z);
            __half2 ow1 = *reinterpret_cast<const __half2*>(&pk.w);

            lh  = __hadd2(lh, w);                  // weights >= 0
            d0h = __hfma2(w, ow0, d0h);
            d1h = __hfma2(w, ow1, d1h);
        }

        // flush group sums to fp32
        float2 t;
        t = __half22float2(lh);  la  += t.x;  lb  += t.y;
        t = __half22float2(d0h); d0a += t.x;  d0b += t.y;
        t = __half22float2(d1h); d1a += t.x;  d1b += t.y;
    }

    // ---- write partials ----
    g_partial[split * B_TOT + b0] = make_float4(la, d0a, d1a, 0.f);
    g_partial[split * B_TOT + b1] = make_float4(lb, d0b, d1b, 0.f);

    // ---- last-block finalize (deterministic fixed-order summation) ----
    __threadfence();
    __syncthreads();
    if (tid == 0) {
        int old = atomicAdd(&g_cnt[grp], 1);
        s_flag = (old == NSPLIT - 1);
    }
    __syncthreads();

    if (s_flag) {
        __threadfence();
        #pragma unroll
        for (int e = 0; e < 2; e++) {
            const int b = (e == 0) ? b0 : b1;
            float l = 0.f, s0 = 0.f, s1 = 0.f;
            #pragma unroll
            for (int s = 0; s < NSPLIT; s++) {
                float4 p = __ldcg(&g_partial[s * B_TOT + b]);
                l += p.x; s0 += p.y; s1 += p.z;
            }
            float inv = __fdividef(1.0f, fmaxf(l, EPS_F));
            float o0 = tanhf(s0 * inv) * 4.0f;            // scale 4.0, center 0.0
            float o1 = tanhf(s1 * inv) * 0.75f + 0.75f;   // scale .75, center .75
            reinterpret_cast<float2*>(out)[b] = make_float2(o0, o1);
        }
        if (tid == 0) g_cnt[grp] = 0;   // reset for next graph replay
    }
}

// ---------------------------------------------------------------------------
extern "C" void kernel_launch(void* const* d_in, const int* in_sizes, int n_in,
                              void* d_out, int out_size) {
    const float* x            = (const float*)d_in[0];
    const float* mf_centers   = (const float*)d_in[1];
    const float* mf_scales    = (const float*)d_in[2];
    const float* out_centers  = (const float*)d_in[3];
    const int*   input_rules  = (const int*)d_in[4];
    const int*   output_rules = (const int*)d_in[5];

    dim3 grid(NGROUP, NSPLIT);
    anfis_fused_kernel<<<grid, TPB>>>(x, mf_centers, mf_scales, out_centers,
                                      input_rules, output_rules, (float*)d_out);
}

// round 16
// speedup vs baseline: 1.5147x; 1.4102x over previous
#include <cuda_runtime.h>
#include <cuda_fp16.h>
#include <stdint.h>

#define B_TOT   16384
#define N_IN    6
#define N_MF    5
#define N_FUZZ  30
#define N_RULES 2048
#define NSPLIT  16
#define RPS     (N_RULES / NSPLIT)   // 128 rules per split
#define TPB     128
#define EPB     256                  // 2 elems per thread (half2)
#define NGROUP  (B_TOT / EPB)        // 64
#define EPS_F   1e-12f
#define SQRT_LOG2E 1.2011224087864498f   // sqrt(log2(e))
#define GRP_RULES 8                  // rules per fp16 accumulation group

// Scratch (__device__ globals: no allocation allowed)
__device__ float4 g_partial[NSPLIT * B_TOT];   // {l1, d0, d1, pad}
__device__ int    g_cnt[NGROUP];               // zero-init; reset after use

static __device__ __forceinline__ float ex2(float v) {
    float r; asm("ex2.approx.ftz.f32 %0, %1;" : "=f"(r) : "f"(v)); return r;
}

// ---------------------------------------------------------------------------
// Single fused kernel — the measured-best configuration (R12).
//  - Fuzz table in SMEM as half2 {fuzz[b0], fuzz[b1]}, b1 = b0+128; one
//    LDS.32 gather serves 2 elems; bank = tid mod 32 -> conflict-free.
//  - Rule record uint4: {x: 4 bytes of 2*idx, y: 2 bytes of 2*idx,
//    z: half2(ow0,ow0), w: half2(ow1,ow1)}. __byte_perm(0, word, 0x004k)
//    yields (2*idx)<<8 = idx<<9 (512B row offset) in ONE instruction;
//    PRMT rides the idle ALU pipe (measured free vs an extra LDS).
//  - Accumulation: per rule 1 HADD2 + 2 HFMA2 in fp16; group sums of
//    GRP_RULES rules flushed to fp32. Rule-level rounding is zero-mean;
//    measured rel_err 7.47e-4 (deterministic: fixed seed + fixed order).
//  - Last-arriving split block per group finalizes (deterministic order).
// ---------------------------------------------------------------------------
__global__ __launch_bounds__(TPB) void anfis_fused_kernel(
    const float* __restrict__ x,
    const float* __restrict__ mf_centers,
    const float* __restrict__ mf_scales,
    const float* __restrict__ out_centers,
    const int*   __restrict__ input_rules,
    const int*   __restrict__ output_rules,
    float* __restrict__ out)
{
    __shared__ __half2 s_fuzz[N_FUZZ * TPB];  // 15 KB
    __shared__ uint4   s_pk[RPS];             // 2 KB: one record per rule
    __shared__ float2  s_cs[N_FUZZ];          // {c*a, a}
    __shared__ int     s_flag;

    const int tid   = threadIdx.x;
    const int grp   = blockIdx.x;
    const int split = blockIdx.y;
    const int b0    = grp * EPB + tid;
    const int b1    = b0 + TPB;

    // ---- stage this split's rules: byte-packed 2*idx + half2-dup ow ----
    if (tid < RPS) {
        const int r = split * RPS + tid;
        const int* ir = input_rules + r * N_IN;
        unsigned w0 = ((unsigned)ir[0] * 2)
                    | (((unsigned)ir[1] * 2) << 8)
                    | (((unsigned)ir[2] * 2) << 16)
                    | (((unsigned)ir[3] * 2) << 24);
        unsigned w1 = ((unsigned)ir[4] * 2)
                    | (((unsigned)ir[5] * 2) << 8);
        float ow0 = out_centers[output_rules[r * 2 + 0]];
        float ow1 = out_centers[output_rules[r * 2 + 1]];
        __half2 ow0h = __floats2half2_rn(ow0, ow0);
        __half2 ow1h = __floats2half2_rn(ow1, ow1);
        s_pk[tid] = make_uint4(w0, w1,
                               *reinterpret_cast<uint32_t*>(&ow0h),
                               *reinterpret_cast<uint32_t*>(&ow1h));
    }
    // ---- membership-function constants: a = sqrt(log2e)/s ----
    if (tid < N_FUZZ) {
        float c = mf_centers[tid];
        float s = mf_scales[tid];
        float a = __fdividef(SQRT_LOG2E, s);
        s_cs[tid] = make_float2(c * a, a);
    }
    __syncthreads();

    // ---- fuzzify both batch elems: exp(-z^2) = ex2(-(x*a - c*a)^2) ----
    {
        float xa[N_IN], xb[N_IN];
        #pragma unroll
        for (int i = 0; i < N_IN; i++) {
            xa[i] = x[b0 * N_IN + i];
            xb[i] = x[b1 * N_IN + i];
        }
        #pragma unroll
        for (int i = 0; i < N_IN; i++) {
            #pragma unroll
            for (int j = 0; j < N_MF; j++) {
                float2 cs = s_cs[i * N_MF + j];      // LDS.64 broadcast
                float ta = fmaf(xa[i], cs.y, -cs.x);
                float tb = fmaf(xb[i], cs.y, -cs.x);
                s_fuzz[(i * N_MF + j) * TPB + tid] =
                    __floats2half2_rn(ex2(-ta * ta), ex2(-tb * tb));
            }
        }
    }
    __syncthreads();

    // ---- rule loop: 1 LDS.128 bcast + 6 LDS.32 gathers per rule;
    //      fp16 group accumulators flushed to fp32 every GRP_RULES rules ----
    const char* fb = reinterpret_cast<const char*>(s_fuzz) + tid * 4;
    float la = 0.f, lb = 0.f;
    float d0a = 0.f, d0b = 0.f;
    float d1a = 0.f, d1b = 0.f;

    const __half2 hzero = __float2half2_rn(0.f);

    for (int kb = 0; kb < RPS; kb += GRP_RULES) {
        __half2 lh  = hzero;
        __half2 d0h = hzero;
        __half2 d1h = hzero;

        #pragma unroll
        for (int u = 0; u < GRP_RULES; u++) {
            const uint4 pk = s_pk[kb + u];         // single LDS.128 broadcast

            // __byte_perm(0, w, 0x004k): byte_k(w) << 8 = (2*idx)<<8 = idx<<9
            __half2 f0 = *reinterpret_cast<const __half2*>(fb + __byte_perm(0u, pk.x, 0x0040));
            __half2 f1 = *reinterpret_cast<const __half2*>(fb + __byte_perm(0u, pk.x, 0x0050));
            __half2 f2 = *reinterpret_cast<const __half2*>(fb + __byte_perm(0u, pk.x, 0x0060));
            __half2 f3 = *reinterpret_cast<const __half2*>(fb + __byte_perm(0u, pk.x, 0x0070));
            __half2 f4 = *reinterpret_cast<const __half2*>(fb + __byte_perm(0u, pk.y, 0x0040));
            __half2 f5 = *reinterpret_cast<const __half2*>(fb + __byte_perm(0u, pk.y, 0x0050));

            __half2 w = __hmin2(__hmin2(__hmin2(f0, f1), __hmin2(f2, f3)),
                                __hmin2(f4, f5));

            __half2 ow0 = *reinterpret_cast<const __half2*>(&pk.z);
            __half2 ow1 = *reinterpret_cast<const __half2*>(&pk.w);

            lh  = __hadd2(lh, w);                  // weights >= 0
            d0h = __hfma2(w, ow0, d0h);
            d1h = __hfma2(w, ow1, d1h);
        }

        // flush group sums to fp32
        float2 t;
        t = __half22float2(lh);  la  += t.x;  lb  += t.y;
        t = __half22float2(d0h); d0a += t.x;  d0b += t.y;
        t = __half22float2(d1h); d1a += t.x;  d1b += t.y;
    }

    // ---- write partials ----
    g_partial[split * B_TOT + b0] = make_float4(la, d0a, d1a, 0.f);
    g_partial[split * B_TOT + b1] = make_float4(lb, d0b, d1b, 0.f);

    // ---- last-block finalize (deterministic fixed-order summation) ----
    __threadfence();
    __syncthreads();
    if (tid == 0) {
        int old = atomicAdd(&g_cnt[grp], 1);
        s_flag = (old == NSPLIT - 1);
    }
    __syncthreads();

    if (s_flag) {
        __threadfence();
        #pragma unroll
        for (int e = 0; e < 2; e++) {
            const int b = (e == 0) ? b0 : b1;
            float l = 0.f, s0 = 0.f, s1 = 0.f;
            #pragma unroll
            for (int s = 0; s < NSPLIT; s++) {
                float4 p = __ldcg(&g_partial[s * B_TOT + b]);
                l += p.x; s0 += p.y; s1 += p.z;
            }
            float inv = __fdividef(1.0f, fmaxf(l, EPS_F));
            float o0 = tanhf(s0 * inv) * 4.0f;            // scale 4.0, center 0.0
            float o1 = tanhf(s1 * inv) * 0.75f + 0.75f;   // scale .75, center .75
            reinterpret_cast<float2*>(out)[b] = make_float2(o0, o1);
        }
        if (tid == 0) g_cnt[grp] = 0;   // reset for next graph replay
    }
}

// ---------------------------------------------------------------------------
extern "C" void kernel_launch(void* const* d_in, const int* in_sizes, int n_in,
                              void* d_out, int out_size) {
    const float* x            = (const float*)d_in[0];
    const float* mf_centers   = (const float*)d_in[1];
    const float* mf_scales    = (const float*)d_in[2];
    const float* out_centers  = (const float*)d_in[3];
    const int*   input_rules  = (const int*)d_in[4];
    const int*   output_rules = (const int*)d_in[5];

    dim3 grid(NGROUP, NSPLIT);
    anfis_fused_kernel<<<grid, TPB>>>(x, mf_centers, mf_scales, out_centers,
                                      input_rules, output_rules, (float*)d_out);
}

// round 17
// speedup vs baseline: 1.6434x; 1.0850x over previous
#include <cuda_runtime.h>
#include <cuda_fp16.h>
#include <stdint.h>

#define B_TOT   16384
#define N_IN    6
#define N_MF    5
#define N_FUZZ  30
#define N_RULES 2048
#define NSPLIT  16
#define RPS     (N_RULES / NSPLIT)   // 128 rules per split
#define TPB     128
#define EPB     256                  // 2 elems per thread (half2)
#define NGROUP  (B_TOT / EPB)        // 64
#define EPS_F   1e-12f
#define SQRT_LOG2E 1.2011224087864498f   // sqrt(log2(e))
#define GRP_RULES 8                  // rules per fp16 accumulation group

// Scratch (__device__ globals: no allocation allowed)
__device__ float4 g_partial[NSPLIT * B_TOT];   // {l1, d0, d1, pad}
__device__ int    g_cnt[NGROUP];               // zero-init; reset after use

static __device__ __forceinline__ float ex2(float v) {
    float r; asm("ex2.approx.ftz.f32 %0, %1;" : "=f"(r) : "f"(v)); return r;
}

// One 8-rule fp16 accumulation group (independent chains; caller interleaves).
static __device__ __forceinline__ void rule_group(
    const uint4* __restrict__ pk_base, const char* __restrict__ fb,
    __half2& lh, __half2& d0h, __half2& d1h)
{
    #pragma unroll
    for (int u = 0; u < GRP_RULES; u++) {
        const uint4 pk = pk_base[u];               // single LDS.128 broadcast

        // __byte_perm(0, w, 0x004k): byte_k(w) << 8 = (2*idx)<<8 = idx<<9
        __half2 f0 = *reinterpret_cast<const __half2*>(fb + __byte_perm(0u, pk.x, 0x0040));
        __half2 f1 = *reinterpret_cast<const __half2*>(fb + __byte_perm(0u, pk.x, 0x0050));
        __half2 f2 = *reinterpret_cast<const __half2*>(fb + __byte_perm(0u, pk.x, 0x0060));
        __half2 f3 = *reinterpret_cast<const __half2*>(fb + __byte_perm(0u, pk.x, 0x0070));
        __half2 f4 = *reinterpret_cast<const __half2*>(fb + __byte_perm(0u, pk.y, 0x0040));
        __half2 f5 = *reinterpret_cast<const __half2*>(fb + __byte_perm(0u, pk.y, 0x0050));

        __half2 w = __hmin2(__hmin2(__hmin2(f0, f1), __hmin2(f2, f3)),
                            __hmin2(f4, f5));

        __half2 ow0 = *reinterpret_cast<const __half2*>(&pk.z);
        __half2 ow1 = *reinterpret_cast<const __half2*>(&pk.w);

        lh  = __hadd2(lh, w);                      // weights >= 0
        d0h = __hfma2(w, ow0, d0h);
        d1h = __hfma2(w, ow1, d1h);
    }
}

// ---------------------------------------------------------------------------
// Single fused kernel — R12 configuration + dual-group ILP in the rule loop.
//  - Fuzz table in SMEM as half2 {fuzz[b0], fuzz[b1]}, b1 = b0+128; one
//    LDS.32 gather serves 2 elems; bank = tid mod 32 -> conflict-free.
//  - Rule record uint4: {4 bytes of 2*idx, 2 bytes of 2*idx,
//    half2(ow0,ow0), half2(ow1,ow1)}; PRMT extraction rides the idle ALU.
//  - Rule loop processes TWO independent 8-rule groups per iteration
//    (separate fp16 accumulator sets) so the A-group flush overlaps the
//    B-group loads; fp32 flush order unchanged -> bit-identical result.
//  - Last-arriving split block per group finalizes (deterministic order).
// ---------------------------------------------------------------------------
__global__ __launch_bounds__(TPB) void anfis_fused_kernel(
    const float* __restrict__ x,
    const float* __restrict__ mf_centers,
    const float* __restrict__ mf_scales,
    const float* __restrict__ out_centers,
    const int*   __restrict__ input_rules,
    const int*   __restrict__ output_rules,
    float* __restrict__ out)
{
    __shared__ __half2 s_fuzz[N_FUZZ * TPB];  // 15 KB
    __shared__ uint4   s_pk[RPS];             // 2 KB: one record per rule
    __shared__ float2  s_cs[N_FUZZ];          // {c*a, a}
    __shared__ int     s_flag;

    const int tid   = threadIdx.x;
    const int grp   = blockIdx.x;
    const int split = blockIdx.y;
    const int b0    = grp * EPB + tid;
    const int b1    = b0 + TPB;

    // ---- stage this split's rules: byte-packed 2*idx + half2-dup ow ----
    if (tid < RPS) {
        const int r = split * RPS + tid;
        const int* ir = input_rules + r * N_IN;
        unsigned w0 = ((unsigned)ir[0] * 2)
                    | (((unsigned)ir[1] * 2) << 8)
                    | (((unsigned)ir[2] * 2) << 16)
                    | (((unsigned)ir[3] * 2) << 24);
        unsigned w1 = ((unsigned)ir[4] * 2)
                    | (((unsigned)ir[5] * 2) << 8);
        float ow0 = out_centers[output_rules[r * 2 + 0]];
        float ow1 = out_centers[output_rules[r * 2 + 1]];
        __half2 ow0h = __floats2half2_rn(ow0, ow0);
        __half2 ow1h = __floats2half2_rn(ow1, ow1);
        s_pk[tid] = make_uint4(w0, w1,
                               *reinterpret_cast<uint32_t*>(&ow0h),
                               *reinterpret_cast<uint32_t*>(&ow1h));
    }
    // ---- membership-function constants: a = sqrt(log2e)/s ----
    if (tid < N_FUZZ) {
        float c = mf_centers[tid];
        float s = mf_scales[tid];
        float a = __fdividef(SQRT_LOG2E, s);
        s_cs[tid] = make_float2(c * a, a);
    }
    __syncthreads();

    // ---- fuzzify both batch elems: exp(-z^2) = ex2(-(x*a - c*a)^2) ----
    {
        float xa[N_IN], xb[N_IN];
        #pragma unroll
        for (int i = 0; i < N_IN; i++) {
            xa[i] = x[b0 * N_IN + i];
            xb[i] = x[b1 * N_IN + i];
        }
        #pragma unroll
        for (int i = 0; i < N_IN; i++) {
            #pragma unroll
            for (int j = 0; j < N_MF; j++) {
                float2 cs = s_cs[i * N_MF + j];      // LDS.64 broadcast
                float ta = fmaf(xa[i], cs.y, -cs.x);
                float tb = fmaf(xb[i], cs.y, -cs.x);
                s_fuzz[(i * N_MF + j) * TPB + tid] =
                    __floats2half2_rn(ex2(-ta * ta), ex2(-tb * tb));
            }
        }
    }
    __syncthreads();

    // ---- rule loop: two independent 8-rule groups per iteration ----
    const char* fb = reinterpret_cast<const char*>(s_fuzz) + tid * 4;
    float la = 0.f, lb = 0.f;
    float d0a = 0.f, d0b = 0.f;
    float d1a = 0.f, d1b = 0.f;

    const __half2 hzero = __float2half2_rn(0.f);

    for (int kb = 0; kb < RPS; kb += 2 * GRP_RULES) {
        __half2 lhA = hzero, d0hA = hzero, d1hA = hzero;
        __half2 lhB = hzero, d0hB = hzero, d1hB = hzero;

        rule_group(&s_pk[kb],             fb, lhA, d0hA, d1hA);
        rule_group(&s_pk[kb + GRP_RULES], fb, lhB, d0hB, d1hB);

        // flush in original rule order (A then B): bit-identical to R12
        float2 t;
        t = __half22float2(lhA);  la  += t.x;  lb  += t.y;
        t = __half22float2(d0hA); d0a += t.x;  d0b += t.y;
        t = __half22float2(d1hA); d1a += t.x;  d1b += t.y;
        t = __half22float2(lhB);  la  += t.x;  lb  += t.y;
        t = __half22float2(d0hB); d0a += t.x;  d0b += t.y;
        t = __half22float2(d1hB); d1a += t.x;  d1b += t.y;
    }

    // ---- write partials ----
    g_partial[split * B_TOT + b0] = make_float4(la, d0a, d1a, 0.f);
    g_partial[split * B_TOT + b1] = make_float4(lb, d0b, d1b, 0.f);

    // ---- last-block finalize (deterministic fixed-order summation) ----
    __threadfence();
    __syncthreads();
    if (tid == 0) {
        int old = atomicAdd(&g_cnt[grp], 1);
        s_flag = (old == NSPLIT - 1);
    }
    __syncthreads();

    if (s_flag) {
        __threadfence();
        #pragma unroll
        for (int e = 0; e < 2; e++) {
            const int b = (e == 0) ? b0 : b1;
            float l = 0.f, s0 = 0.f, s1 = 0.f;
            #pragma unroll
            for (int s = 0; s < NSPLIT; s++) {
                float4 p = __ldcg(&g_partial[s * B_TOT + b]);
                l += p.x; s0 += p.y; s1 += p.z;
            }
            float inv = __fdividef(1.0f, fmaxf(l, EPS_F));
            float o0 = tanhf(s0 * inv) * 4.0f;            // scale 4.0, center 0.0
            float o1 = tanhf(s1 * inv) * 0.75f + 0.75f;   // scale .75, center .75
            reinterpret_cast<float2*>(out)[b] = make_float2(o0, o1);
        }
        if (tid == 0) g_cnt[grp] = 0;   // reset for next graph replay
    }
}

// ---------------------------------------------------------------------------
extern "C" void kernel_launch(void* const* d_in, const int* in_sizes, int n_in,
                              void* d_out, int out_size) {
    const float* x            = (const float*)d_in[0];
    const float* mf_centers   = (const float*)d_in[1];
    const float* mf_scales    = (const float*)d_in[2];
    const float* out_centers  = (const float*)d_in[3];
    const int*   input_rules  = (const int*)d_in[4];
    const int*   output_rules = (const int*)d_in[5];

    dim3 grid(NGROUP, NSPLIT);
    anfis_fused_kernel<<<grid, TPB>>>(x, mf_centers, mf_scales, out_centers,
                                      input_rules, output_rules, (float*)d_out);
}